// round 1
// baseline (speedup 1.0000x reference)
#include <cuda_runtime.h>
#include <cuda_bf16.h>

#define OUT_SZ 7
#define NCH 256

__global__ __launch_bounds__(NCH, 8)
void roialign_kernel(const float* __restrict__ p2,
                     const float* __restrict__ p3,
                     const float* __restrict__ p4,
                     const float* __restrict__ p5,
                     const float* __restrict__ rois,
                     float* __restrict__ out,
                     int n_rois)
{
    int roi = blockIdx.x;
    if (roi >= n_rois) return;
    int c = threadIdx.x;

    // rois row: [batch, x1, y1, x2, y2]
    const float* r = rois + (size_t)roi * 5;
    float bf  = r[0];
    float rx1 = r[1], ry1 = r[2], rx2 = r[3], ry2 = r[4];
    int b = (int)bf;

    float roi_w = rx2 - rx1;
    float roi_h = ry2 - ry1;
    float lvl = 4.0f + log2f(sqrtf(roi_h * roi_w) / 224.0f);
    int level = (int)rintf(lvl);
    level = level < 2 ? 2 : (level > 5 ? 5 : level);

    const float* fm;
    int H;            // H == W at every level
    float inv_stride;
    switch (level) {
        case 2: fm = p2; H = 256; inv_stride = 1.0f / 4.0f;  break;
        case 3: fm = p3; H = 128; inv_stride = 1.0f / 8.0f;  break;
        case 4: fm = p4; H = 64;  inv_stride = 1.0f / 16.0f; break;
        default: fm = p5; H = 32; inv_stride = 1.0f / 32.0f; break;
    }
    int W = H;
    float Hm1 = (float)(H - 1);
    float Wm1 = (float)(W - 1);

    // crop_and_resize reads boxes as [y1,x1,y2,x2]; roi_align passes
    // [x1,y1,x2,y2]*(1/stride). So box_y1 = rx1/stride, box_x1 = ry1/stride, etc.
    float by1 = rx1 * inv_stride;
    float bx1 = ry1 * inv_stride;
    float by2 = rx2 * inv_stride;
    float bx2 = ry2 * inv_stride;

    float h_scale = (by2 - by1) * Hm1 / (float)(OUT_SZ - 1);
    float w_scale = (bx2 - bx1) * Wm1 / (float)(OUT_SZ - 1);
    float y_base = by1 * Hm1;
    float x_base = bx1 * Wm1;

    const float* fm_b = fm + (size_t)b * H * W * NCH;
    float* out_roi = out + (size_t)roi * OUT_SZ * OUT_SZ * NCH;

    // Precompute per-axis interpolation data (same for all threads; cheap).
    int   y0a[OUT_SZ], yca[OUT_SZ];
    float lya[OUT_SZ];
    bool  vya[OUT_SZ];
    int   x0a[OUT_SZ], xca[OUT_SZ];
    float lxa[OUT_SZ];
    bool  vxa[OUT_SZ];

#pragma unroll
    for (int i = 0; i < OUT_SZ; i++) {
        float in_y = y_base + (float)i * h_scale;
        vya[i] = (in_y >= 0.0f) && (in_y <= Hm1);
        float fy = floorf(in_y);
        float cy = ceilf(in_y);
        float fy_c = fminf(fmaxf(fy, 0.0f), Hm1);
        float cy_c = fminf(fmaxf(cy, 0.0f), Hm1);
        y0a[i] = (int)fy_c;
        yca[i] = (int)cy_c;
        lya[i] = in_y - fy;

        float in_x = x_base + (float)i * w_scale;
        vxa[i] = (in_x >= 0.0f) && (in_x <= Wm1);
        float fx = floorf(in_x);
        float cx = ceilf(in_x);
        float fx_c = fminf(fmaxf(fx, 0.0f), Wm1);
        float cx_c = fminf(fmaxf(cx, 0.0f), Wm1);
        x0a[i] = (int)fx_c;
        xca[i] = (int)cx_c;
        lxa[i] = in_x - fx;
    }

#pragma unroll 1
    for (int i = 0; i < OUT_SZ; i++) {
        int y0 = y0a[i], yc = yca[i];
        float ly = lya[i];
        bool vy = vya[i];
        const float* row0 = fm_b + (size_t)y0 * W * NCH;
        const float* row1 = fm_b + (size_t)yc * W * NCH;
#pragma unroll 1
        for (int j = 0; j < OUT_SZ; j++) {
            float v = 0.0f;
            if (vy && vxa[j]) {
                int x0 = x0a[j], xc = xca[j];
                float lx = lxa[j];
                float tl = __ldg(row0 + (size_t)x0 * NCH + c);
                float tr = __ldg(row0 + (size_t)xc * NCH + c);
                float bl = __ldg(row1 + (size_t)x0 * NCH + c);
                float br = __ldg(row1 + (size_t)xc * NCH + c);
                float top = tl + (tr - tl) * lx;
                float bot = bl + (br - bl) * lx;
                v = top + (bot - top) * ly;
            }
            out_roi[(i * OUT_SZ + j) * NCH + c] = v;
        }
    }
}

extern "C" void kernel_launch(void* const* d_in, const int* in_sizes, int n_in,
                              void* d_out, int out_size)
{
    const float* p2   = (const float*)d_in[0];
    const float* p3   = (const float*)d_in[1];
    const float* p4   = (const float*)d_in[2];
    const float* p5   = (const float*)d_in[3];
    const float* rois = (const float*)d_in[4];
    float* out = (float*)d_out;
    int n_rois = in_sizes[4] / 5;

    roialign_kernel<<<n_rois, NCH>>>(p2, p3, p4, p5, rois, out, n_rois);
}

// round 2
// speedup vs baseline: 1.7944x; 1.7944x over previous
#include <cuda_runtime.h>
#include <cuda_bf16.h>

#define OUT_SZ 7
#define NCELL (OUT_SZ * OUT_SZ)
#define NCH 256
#define NQ (NCH / 4)      // 64 float4 per channel row
#define SLOTS 4           // cells processed concurrently per block

__global__ __launch_bounds__(NQ * SLOTS, 8)
void roialign_kernel(const float* __restrict__ p2,
                     const float* __restrict__ p3,
                     const float* __restrict__ p4,
                     const float* __restrict__ p5,
                     const float* __restrict__ rois,
                     float* __restrict__ out,
                     int n_rois)
{
    int roi = blockIdx.x;
    if (roi >= n_rois) return;

    int tid  = threadIdx.x;
    int cq   = tid & (NQ - 1);   // channel quad 0..63
    int slot = tid >> 6;         // 0..3

    // rois row: [batch, x1, y1, x2, y2]
    const float* r = rois + (size_t)roi * 5;
    float bf  = __ldg(r + 0);
    float rx1 = __ldg(r + 1), ry1 = __ldg(r + 2);
    float rx2 = __ldg(r + 3), ry2 = __ldg(r + 4);
    int b = (int)bf;

    float roi_w = rx2 - rx1;
    float roi_h = ry2 - ry1;
    float lvl = 4.0f + log2f(sqrtf(roi_h * roi_w) / 224.0f);
    int level = (int)rintf(lvl);
    level = level < 2 ? 2 : (level > 5 ? 5 : level);

    const float* fm;
    int H;            // H == W at every level
    float inv_stride;
    switch (level) {
        case 2: fm = p2; H = 256; inv_stride = 1.0f / 4.0f;  break;
        case 3: fm = p3; H = 128; inv_stride = 1.0f / 8.0f;  break;
        case 4: fm = p4; H = 64;  inv_stride = 1.0f / 16.0f; break;
        default: fm = p5; H = 32; inv_stride = 1.0f / 32.0f; break;
    }
    int W = H;
    float Hm1 = (float)(H - 1);
    float Wm1 = (float)(W - 1);

    // crop_and_resize reads boxes as [y1,x1,y2,x2]; roi_align passes
    // [x1,y1,x2,y2]*(1/stride). So box_y1 = rx1/stride, box_x1 = ry1/stride.
    float by1 = rx1 * inv_stride;
    float bx1 = ry1 * inv_stride;
    float by2 = rx2 * inv_stride;
    float bx2 = ry2 * inv_stride;

    float h_scale = (by2 - by1) * Hm1 / (float)(OUT_SZ - 1);
    float w_scale = (bx2 - bx1) * Wm1 / (float)(OUT_SZ - 1);
    float y_base = by1 * Hm1;
    float x_base = bx1 * Wm1;

    const float4* fm_b = (const float4*)(fm + (size_t)b * H * W * NCH);
    float4* out_roi = (float4*)(out + (size_t)roi * NCELL * NCH);

#pragma unroll 1
    for (int cell = slot; cell < NCELL; cell += SLOTS) {
        int i = cell / OUT_SZ;
        int j = cell - i * OUT_SZ;

        float in_y = fmaf((float)i, h_scale, y_base);
        float in_x = fmaf((float)j, w_scale, x_base);
        bool valid = (in_y >= 0.0f) & (in_y <= Hm1) &
                     (in_x >= 0.0f) & (in_x <= Wm1);

        float4 v = make_float4(0.f, 0.f, 0.f, 0.f);
        if (valid) {
            float fy = floorf(in_y);
            float fx = floorf(in_x);
            float ly = in_y - fy;
            float lx = in_x - fx;
            // in-range ⇒ floor in [0,H-1]; ceil only needs upper clip
            int y0 = (int)fy;
            int x0 = (int)fx;
            int yc = (int)fminf(ceilf(in_y), Hm1);
            int xc = (int)fminf(ceilf(in_x), Wm1);

            const float4* row0 = fm_b + (size_t)y0 * W * NQ;
            const float4* row1 = fm_b + (size_t)yc * W * NQ;
            float4 tl = __ldg(row0 + x0 * NQ + cq);
            float4 tr = __ldg(row0 + xc * NQ + cq);
            float4 bl = __ldg(row1 + x0 * NQ + cq);
            float4 br = __ldg(row1 + xc * NQ + cq);

            float4 top, bot;
            top.x = fmaf(tr.x - tl.x, lx, tl.x);
            top.y = fmaf(tr.y - tl.y, lx, tl.y);
            top.z = fmaf(tr.z - tl.z, lx, tl.z);
            top.w = fmaf(tr.w - tl.w, lx, tl.w);
            bot.x = fmaf(br.x - bl.x, lx, bl.x);
            bot.y = fmaf(br.y - bl.y, lx, bl.y);
            bot.z = fmaf(br.z - bl.z, lx, bl.z);
            bot.w = fmaf(br.w - bl.w, lx, bl.w);
            v.x = fmaf(bot.x - top.x, ly, top.x);
            v.y = fmaf(bot.y - top.y, ly, top.y);
            v.z = fmaf(bot.z - top.z, ly, top.z);
            v.w = fmaf(bot.w - top.w, ly, top.w);
        }
        out_roi[cell * NQ + cq] = v;
    }
}

extern "C" void kernel_launch(void* const* d_in, const int* in_sizes, int n_in,
                              void* d_out, int out_size)
{
    const float* p2   = (const float*)d_in[0];
    const float* p3   = (const float*)d_in[1];
    const float* p4   = (const float*)d_in[2];
    const float* p5   = (const float*)d_in[3];
    const float* rois = (const float*)d_in[4];
    float* out = (float*)d_out;
    int n_rois = in_sizes[4] / 5;

    roialign_kernel<<<n_rois, NQ * SLOTS>>>(p2, p3, p4, p5, rois, out, n_rois);
}